// round 12
// baseline (speedup 1.0000x reference)
#include <cuda_runtime.h>
#include <cuda_bf16.h>

// Problem: MultinomialCELoss
//   x: [N=8, Q=441, H=128, W=128] f32, y: [N=8, 2, H=128, W=128] f32
//   out[w] = -sum_{n,h} log( x[n, idx(n,h,w), h, w] )
//
// R12: R11 (one CTA per output element, zero inter-CTA communication) WON
// (8.7 -> 6.66us) but sits at occ 26% — still latency-bound. Double resident
// parallelism: 1024 threads/CTA, one (n,h) row per thread (4096 warps ~ 28/SM,
// the occupancy that made the bare gather run at 1.9us in R3). Same
// no-atomic/no-fence/single-node structure; block tree gains one level.

#define N_  8
#define Q_  441
#define H_  128
#define W_  128
#define HW_ (H_ * W_)
#define NBINS 21
#define TPB 1024                 // one thread per (n,h) row

__device__ __forceinline__ int ab_bin(float v) {
    // Match JAX f32 semantics: floor((v + 110) / 10), clipped to [0,20].
    // __fdiv_rn keeps IEEE division even under fast-math (bin boundaries).
    float q = floorf(__fdiv_rn(v + 110.0f, 10.0f));
    int qi = (int)q;
    qi = qi < 0 ? 0 : qi;
    qi = qi > (NBINS - 1) ? (NBINS - 1) : qi;
    return qi;
}

__global__ __launch_bounds__(TPB) void mce_column_kernel(
    const float* __restrict__ x,
    const float* __restrict__ y,
    float* __restrict__ out)
{
    const int w = blockIdx.x;     // 0..127: this CTA owns out[w]
    const int t = threadIdx.x;    // 0..1023 = flattened (n,h) row
    const int n = t >> 7;
    const int h = t & (H_ - 1);
    const int hw = h * W_ + w;

    float ya = y[(size_t)(n * 2 + 0) * HW_ + hw];
    float yb = y[(size_t)(n * 2 + 1) * HW_ + hw];
    const int idx = ab_bin(ya) * NBINS + ab_bin(yb);

    float v = x[((size_t)n * Q_ + idx) * HW_ + hw];
    float s = __logf(v);

    // Intra-block tree: warp shuffle, then 32 warp partials through smem.
    #pragma unroll
    for (int off = 16; off > 0; off >>= 1)
        s += __shfl_down_sync(0xffffffffu, s, off);

    __shared__ float red[TPB / 32];          // 32 warp partials
    if ((t & 31) == 0) red[t >> 5] = s;
    __syncthreads();

    if (t < 32) {
        float r = red[t];
        #pragma unroll
        for (int off = 16; off > 0; off >>= 1)
            r += __shfl_down_sync(0xffffffffu, r, off);
        if (t == 0) out[w] = -r;
    }
}

extern "C" void kernel_launch(void* const* d_in, const int* in_sizes, int n_in,
                              void* d_out, int out_size) {
    const float* x = (const float*)d_in[0];
    const float* y = (const float*)d_in[1];
    float* out = (float*)d_out;

    mce_column_kernel<<<W_, TPB>>>(x, y, out);
}

// round 13
// speedup vs baseline: 1.0257x; 1.0257x over previous
#include <cuda_runtime.h>
#include <cuda_bf16.h>

// Problem: MultinomialCELoss
//   x: [N=8, Q=441, H=128, W=128] f32, y: [N=8, 2, H=128, W=128] f32
//   out[w] = -sum_{n,h} log( x[n, idx(n,h,w), h, w] )
//
// R13: lessons — MLP=2 @ ~16 warps/SM wins (R11 vs R12); column layout makes
// y loads 32x-uncoalesced; all previous reduces were slow because the partial
// layout forced either single-SM reads or uncoalesced column reads.
// Fix: row-layout gather kernel (coalesced y, MLP=2, 512 CTAs) that stores
// its partials TRANSPOSED (scattered stores are fire-and-forget, unlike
// scattered loads), so the reduce kernel reads each w's 512 partials as one
// contiguous, L2-hot, fully-coalesced 2KB block per CTA.

#define N_  8
#define Q_  441
#define H_  128
#define W_  128
#define HW_ (H_ * W_)
#define NBINS 21
#define GRIDA 512             // row-pair groups
#define RPT 2                 // rows per thread (MLP=2, R11's winner)

__device__ float g_partial[W_ * GRIDA];   // 256 KB, transposed: [w][b]

__device__ __forceinline__ int ab_bin(float v) {
    // Match JAX f32 semantics: floor((v + 110) / 10), clipped to [0,20].
    // __fdiv_rn keeps IEEE division even under fast-math (bin boundaries).
    float q = floorf(__fdiv_rn(v + 110.0f, 10.0f));
    int qi = (int)q;
    qi = qi < 0 ? 0 : qi;
    qi = qi > (NBINS - 1) ? (NBINS - 1) : qi;
    return qi;
}

// Kernel A: CTA b handles flattened rows {2b, 2b+1}. Thread w:
// 4 coalesced y loads -> 2 batched scattered gathers -> 2 MUFU logs ->
// 1 transposed store partial[w][b]. 512 CTAs ~ 16 warps/SM.
__global__ __launch_bounds__(W_) void mce_gather_kernel(
    const float* __restrict__ x,
    const float* __restrict__ y,
    float* __restrict__ partial)
{
    const int w = threadIdx.x;        // 0..127
    const int b = blockIdx.x;         // 0..511

    int idx[RPT], n_[RPT], hw_[RPT];
    #pragma unroll
    for (int k = 0; k < RPT; k++) {
        const int row = b * RPT + k;  // 0..1023
        const int n = row >> 7;
        const int h = row & (H_ - 1);
        n_[k] = n;
        hw_[k] = h * W_ + w;
        float ya = y[(size_t)(n * 2 + 0) * HW_ + hw_[k]];   // coalesced
        float yb = y[(size_t)(n * 2 + 1) * HW_ + hw_[k]];   // coalesced
        idx[k] = ab_bin(ya) * NBINS + ab_bin(yb);
    }

    float v[RPT];
    #pragma unroll
    for (int k = 0; k < RPT; k++) {
        v[k] = x[((size_t)n_[k] * Q_ + idx[k]) * HW_ + hw_[k]];
    }

    float acc = 0.0f;
    #pragma unroll
    for (int k = 0; k < RPT; k++) acc += __logf(v[k]);

    // Transposed store: fire-and-forget, makes the reduce coalesced.
    partial[w * GRIDA + b] = acc;
}

// Kernel B: CTA w reads its 512 contiguous partials (one coalesced 2KB
// block, L2-hot), tree-reduces, writes out[w] = -sum.
__global__ __launch_bounds__(GRIDA) void mce_reduce_kernel(
    const float* __restrict__ partial,
    float* __restrict__ out)
{
    const int w = blockIdx.x;         // 0..127
    const int t = threadIdx.x;        // 0..511

    float s = partial[w * GRIDA + t];

    #pragma unroll
    for (int off = 16; off > 0; off >>= 1)
        s += __shfl_down_sync(0xffffffffu, s, off);

    __shared__ float red[GRIDA / 32];     // 16 warp partials
    if ((t & 31) == 0) red[t >> 5] = s;
    __syncthreads();

    if (t < 32) {
        float r = (t < GRIDA / 32) ? red[t] : 0.0f;
        #pragma unroll
        for (int off = 8; off > 0; off >>= 1)
            r += __shfl_down_sync(0xffffffffu, r, off);
        if (t == 0) out[w] = -r;
    }
}

extern "C" void kernel_launch(void* const* d_in, const int* in_sizes, int n_in,
                              void* d_out, int out_size) {
    const float* x = (const float*)d_in[0];
    const float* y = (const float*)d_in[1];
    float* out = (float*)d_out;

    float* partial = nullptr;
    cudaGetSymbolAddress((void**)&partial, g_partial);

    mce_gather_kernel<<<GRIDA, W_>>>(x, y, partial);
    mce_reduce_kernel<<<W_, GRIDA>>>(partial, out);
}

// round 14
// speedup vs baseline: 1.3478x; 1.3140x over previous
#include <cuda_runtime.h>
#include <cuda_bf16.h>

// Problem: MultinomialCELoss
//   x: [N=8, Q=441, H=128, W=128] f32, y: [N=8, 2, H=128, W=128] f32
//   out[w] = -sum_{n,h} log( x[n, idx(n,h,w), h, w] )
//
// R14: R11 (one CTA per output, zero inter-CTA sync, MLP=2) is the proven
// winner at 6.66us, and its ncu numbers show it is DRAM-traffic-bound at the
// random-line wall: 2052GB/s x 8.38us = 17MB = 131072 gathers x 128B — the
// .nc/tex load path promotes every 4B gather to a full 128B line fill (32x
// amplification). Single change: route the x gather through ld.global.cg
// (L2-only path, sector-granular fill) to cut gather DRAM bytes ~4x.

#define N_  8
#define Q_  441
#define H_  128
#define W_  128
#define HW_ (H_ * W_)
#define NBINS 21
#define TPB 512
#define ROWS_PER_THREAD 2     // 1024 rows / 512 threads (MLP=2: R11's winner)

__device__ __forceinline__ int ab_bin(float v) {
    // Match JAX f32 semantics: floor((v + 110) / 10), clipped to [0,20].
    // __fdiv_rn keeps IEEE division even under fast-math (bin boundaries).
    float q = floorf(__fdiv_rn(v + 110.0f, 10.0f));
    int qi = (int)q;
    qi = qi < 0 ? 0 : qi;
    qi = qi > (NBINS - 1) ? (NBINS - 1) : qi;
    return qi;
}

__global__ __launch_bounds__(TPB) void mce_column_kernel(
    const float* __restrict__ x,
    const float* __restrict__ y,
    float* __restrict__ out)
{
    const int w = blockIdx.x;     // 0..127: this CTA owns out[w]
    const int t = threadIdx.x;    // 0..511

    // Thread t handles flattened rows t and t+512.
    int idx[ROWS_PER_THREAD], n_[ROWS_PER_THREAD], hw_[ROWS_PER_THREAD];
    #pragma unroll
    for (int k = 0; k < ROWS_PER_THREAD; k++) {
        const int row = t + k * TPB;         // 0..1023
        const int n = row >> 7;
        const int h = row & (H_ - 1);
        n_[k] = n;
        hw_[k] = h * W_ + w;
        float ya = y[(size_t)(n * 2 + 0) * HW_ + hw_[k]];
        float yb = y[(size_t)(n * 2 + 1) * HW_ + hw_[k]];
        idx[k] = ab_bin(ya) * NBINS + ab_bin(yb);
    }

    float v[ROWS_PER_THREAD];
    #pragma unroll
    for (int k = 0; k < ROWS_PER_THREAD; k++) {
        // ld.global.cg: L2-only path, sector-granular fill — avoid the
        // .nc/tex path's 128B line promotion (32x read amplification).
        v[k] = __ldcg(&x[((size_t)n_[k] * Q_ + idx[k]) * HW_ + hw_[k]]);
    }

    float s = 0.0f;
    #pragma unroll
    for (int k = 0; k < ROWS_PER_THREAD; k++) s += __logf(v[k]);

    // Intra-block tree: warp shuffle, then 16 warp sums through smem.
    #pragma unroll
    for (int off = 16; off > 0; off >>= 1)
        s += __shfl_down_sync(0xffffffffu, s, off);

    __shared__ float red[TPB / 32];          // 16 warp partials
    if ((t & 31) == 0) red[t >> 5] = s;
    __syncthreads();

    if (t < 32) {
        float r = (t < TPB / 32) ? red[t] : 0.0f;
        #pragma unroll
        for (int off = 8; off > 0; off >>= 1)
            r += __shfl_down_sync(0xffffffffu, r, off);
        if (t == 0) out[w] = -r;
    }
}

extern "C" void kernel_launch(void* const* d_in, const int* in_sizes, int n_in,
                              void* d_out, int out_size) {
    const float* x = (const float*)d_in[0];
    const float* y = (const float*)d_in[1];
    float* out = (float*)d_out;

    mce_column_kernel<<<W_, TPB>>>(x, y, out);
}